// round 3
// baseline (speedup 1.0000x reference)
#include <cuda_runtime.h>
#include <cuda_bf16.h>
#include <cstdint>

// FWHT n=1024 over x[64,1024,512] f32, single pass, persistent CTAs with a
// cp.async double-buffered smem pipeline.
//
// n = j*32 + i. Phase 1: FWHT_32 over i in registers; smem transpose;
// Phase 2: FWHT_32 over j in registers. Data held as float2 (b64) pairs,
// butterflies via packed add/sub.rn.f32x2.
//
// Tile = (batch b, d-tile of 8 floats): 1024 x 8 f32 = 32 KB. 4096 tiles.
// CTA = 128 threads = (jt in [0,32)) x (dh in [0,4)); each thread owns
// 32 float2 values. Smem = 2 x 32 KB buffers (double buffer).

#define FW_N 1024
#define FW_D 512
#define FW_TILE_F8 4096            // 8-byte slots per tile (1024 rows * 4)
#define FW_THREADS 128
#define FW_NTILES 4096             // 64 batches * 64 d-tiles
#define FW_SMEM_BYTES (2 * FW_TILE_F8 * 8)   // 64 KiB

// packed butterfly: (a,b) -> (a+b, a-b) on two f32 lanes at once
__device__ __forceinline__ void bfly(unsigned long long& a, unsigned long long& b) {
    unsigned long long s, d;
    asm("add.rn.f32x2 %0, %2, %3;\n\t"
        "sub.rn.f32x2 %1, %2, %3;"
        : "=l"(s), "=l"(d)
        : "l"(a), "l"(b));
    a = s; b = d;
}

__device__ __forceinline__ void cp_async8(uint32_t dst_smem, const void* src) {
    asm volatile("cp.async.ca.shared.global [%0], [%1], 8;" :: "r"(dst_smem), "l"(src));
}
__device__ __forceinline__ void cp_commit() {
    asm volatile("cp.async.commit_group;");
}
__device__ __forceinline__ void cp_wait1() {
    asm volatile("cp.async.wait_group 1;");
}
__device__ __forceinline__ void cp_wait0() {
    asm volatile("cp.async.wait_group 0;");
}

// conflict-free slot (in 8-byte units) for logical (row r, float2 column dh)
__device__ __forceinline__ uint32_t slot8(uint32_t r, uint32_t dh) {
    return ((r >> 5) << 7) + (((r & 31u) ^ ((r >> 5) & 3u)) << 2) + dh;
}

__global__ __launch_bounds__(FW_THREADS, 3)
void fwht1024_kernel(const float* __restrict__ x, float* __restrict__ y) {
    extern __shared__ unsigned long long smem8[];   // [2][4096] 8-byte slots

    const uint32_t tid = threadIdx.x;
    const uint32_t dh  = tid & 3;     // float2 column (0..3) of the 8-float d-tile
    const uint32_t jt  = tid >> 2;    // 0..31 : j in phase 1 / i in phase 2

    uint32_t smem_u32;
    asm("{ .reg .u64 t; cvta.to.shared.u64 t, %1; cvt.u32.u64 %0, t; }"
        : "=r"(smem_u32) : "l"(smem8));

    const uint32_t stride = gridDim.x;

    // ---- prologue: prefetch first tile into buffer 0 ----
    uint32_t tile = blockIdx.x;
    if (tile < FW_NTILES) {
        const uint32_t b  = tile >> 6;
        const uint32_t dt = tile & 63u;
        const float* src = x + (size_t)b * (FW_N * FW_D) + dt * 8 + dh * 2;
        const uint32_t dbase = smem_u32;   // buffer 0
#pragma unroll
        for (int i = 0; i < 32; ++i) {
            const uint32_t r = jt * 32 + i;
            cp_async8(dbase + slot8(r, dh) * 8, src + (size_t)r * FW_D);
        }
        cp_commit();
    }

    uint32_t k = 0;  // current buffer
    for (; tile < FW_NTILES; tile += stride) {
        const uint32_t ntile = tile + stride;
        const bool has_next = (ntile < FW_NTILES);

        // ---- prefetch next tile into the other buffer ----
        if (has_next) {
            const uint32_t nb  = ntile >> 6;
            const uint32_t ndt = ntile & 63u;
            const float* src = x + (size_t)nb * (FW_N * FW_D) + ndt * 8 + dh * 2;
            const uint32_t dbase = smem_u32 + (k ^ 1u) * (FW_TILE_F8 * 8);
#pragma unroll
            for (int i = 0; i < 32; ++i) {
                const uint32_t r = jt * 32 + i;
                cp_async8(dbase + slot8(r, dh) * 8, src + (size_t)r * FW_D);
            }
            cp_commit();
            cp_wait1();        // current tile's group is complete
        } else {
            cp_wait0();
        }
        __syncthreads();       // landed data visible to all threads

        unsigned long long* buf = smem8 + (size_t)k * FW_TILE_F8;
        unsigned long long v[32];

        // ---- phase 1: FWHT_32 over i (rows jt*32 + i) ----
#pragma unroll
        for (int i = 0; i < 32; ++i)
            v[i] = buf[slot8(jt * 32 + i, dh)];

#pragma unroll
        for (int h = 1; h < 32; h <<= 1) {
#pragma unroll
            for (int i = 0; i < 32; ++i)
                if ((i & h) == 0) bfly(v[i], v[i | h]);
        }

        // write back to the SAME slots (thread-private, no race)
#pragma unroll
        for (int i = 0; i < 32; ++i)
            buf[slot8(jt * 32 + i, dh)] = v[i];

        __syncthreads();       // transpose visible

        // ---- phase 2: FWHT_32 over j (rows j*32 + it, it == jt) ----
#pragma unroll
        for (int j = 0; j < 32; ++j)
            v[j] = buf[slot8(j * 32 + jt, dh)];

#pragma unroll
        for (int h = 1; h < 32; h <<= 1) {
#pragma unroll
            for (int j = 0; j < 32; ++j)
                if ((j & h) == 0) bfly(v[j], v[j | h]);
        }

        // ---- store (coalesced 32B chunks) ----
        {
            const uint32_t b  = tile >> 6;
            const uint32_t dt = tile & 63u;
            float* dst = y + (size_t)b * (FW_N * FW_D) + dt * 8 + dh * 2;
#pragma unroll
            for (int j = 0; j < 32; ++j) {
                const uint32_t r = j * 32 + jt;
                *reinterpret_cast<unsigned long long*>(dst + (size_t)r * FW_D) = v[j];
            }
        }

        __syncthreads();       // all reads of buf[k] done before it is refilled
        k ^= 1u;
    }
}

extern "C" void kernel_launch(void* const* d_in, const int* in_sizes, int n_in,
                              void* d_out, int out_size) {
    const float* x = (const float*)d_in[0];
    float* y = (float*)d_out;

    cudaFuncSetAttribute(fwht1024_kernel,
                         cudaFuncAttributeMaxDynamicSharedMemorySize,
                         FW_SMEM_BYTES);

    int sms = 148;
    cudaDeviceGetAttribute(&sms, cudaDevAttrMultiProcessorCount, 0);

    dim3 grid(sms * 3);   // persistent, 3 CTAs/SM (64 KiB smem each)
    fwht1024_kernel<<<grid, FW_THREADS, FW_SMEM_BYTES>>>(x, y);
}